// round 1
// baseline (speedup 1.0000x reference)
#include <cuda_runtime.h>
#include <math.h>

// Problem dims
#define BSZ   64
#define NMEM  512
#define WD    64
#define RH    4
#define OUTD  256
#define IND   256
#define IFC   471     // interface size
#define CD    727     // controller dim
#define G3    2181    // 3*CD

// Output layout offsets (concatenated flattened tuple, f32)
#define OFF_Y      0
#define OFF_MN     16384
#define OFF_USAGE  2113536
#define OFF_LN     2146304
#define OFF_WP     18923520
#define OFF_WR     18956288
#define OFF_WW     19087360
#define OFF_HC     19120128

// Scratch (no cudaMalloc allowed)
__device__ float g_mx[128 * G3];
__device__ float g_mh[128 * G3];
__device__ float g_iface[128 * IFC];
__device__ float g_Walloc[BSZ * NMEM];
__device__ float g_Wwsum[BSZ];
__device__ float g_fwdpart[BSZ * 8 * NMEM * RH];
__device__ float g_bwdpart[BSZ * 8 * NMEM * RH];
__device__ float g_fwd[BSZ * NMEM * RH];
__device__ float g_bwd[BSZ * NMEM * RH];

__device__ __forceinline__ float sigmoidf_(float x) { return 1.f / (1.f + expf(-x)); }
__device__ __forceinline__ float softplusf_(float x) { return fmaxf(x, 0.f) + log1pf(expf(-fabsf(x))); }

// ---------------------------------------------------------------------------
// Generic SGEMM: C[M,N] = A[M,K] @ B[K,N] (+ bias[N] optional)
// block (32,32), 32x32 tiles
// ---------------------------------------------------------------------------
__global__ void sgemm_bias(const float* __restrict__ A, const float* __restrict__ B,
                           const float* __restrict__ bias, float* __restrict__ C,
                           int M, int N, int K) {
    __shared__ float As[32][33];
    __shared__ float Bs[32][33];
    int tx = threadIdx.x, ty = threadIdx.y;
    int row = blockIdx.y * 32 + ty;
    int col = blockIdx.x * 32 + tx;
    float acc = 0.f;
    for (int k0 = 0; k0 < K; k0 += 32) {
        As[ty][tx] = (row < M && (k0 + tx) < K) ? A[row * K + k0 + tx] : 0.f;
        Bs[ty][tx] = ((k0 + ty) < K && col < N) ? B[(k0 + ty) * N + col] : 0.f;
        __syncthreads();
#pragma unroll
        for (int kk = 0; kk < 32; kk++) acc += As[ty][kk] * Bs[kk][tx];
        __syncthreads();
    }
    if (row < M && col < N) {
        if (bias) acc += bias[col];
        C[row * N + col] = acc;
    }
}

// ---------------------------------------------------------------------------
// GRU combine: c = z*h + (1-z)*gelu(xh + r*rh) ; rows = 2b+s, 727 cols
// hc_out = d_out + OFF_HC  (shape (64,2,727))
// ---------------------------------------------------------------------------
__global__ void gru_combine(const float* __restrict__ h, float* __restrict__ hc_out) {
    int idx = blockIdx.x * blockDim.x + threadIdx.x;
    if (idx >= 128 * CD) return;
    int row = idx / CD, j = idx % CD;
    const float* mx = g_mx + row * G3;
    const float* mh = g_mh + row * G3;
    float z = sigmoidf_(mx[j] + mh[j]);
    float r = sigmoidf_(mx[CD + j] + mh[CD + j]);
    float hin = mx[2 * CD + j] + r * mh[2 * CD + j];
    float hh = hin * normcdff(hin);   // exact gelu
    float hv = h[idx];
    hc_out[idx] = z * hv + (1.f - z) * hh;
}

// ---------------------------------------------------------------------------
// usage_n = (u + w - u*w) * prod_r (1 - sig(free_g[r]) * W_read[b,n,r])
// ---------------------------------------------------------------------------
__global__ void usage_kernel(const float* __restrict__ W_read,
                             const float* __restrict__ W_write,
                             const float* __restrict__ usage,
                             float* __restrict__ usage_out) {
    int idx = blockIdx.x * blockDim.x + threadIdx.x;
    if (idx >= BSZ * NMEM) return;
    int b = idx >> 9;
    const float* ifw = g_iface + (2 * b + 1) * IFC;
    float ret = 1.f;
#pragma unroll
    for (int r = 0; r < RH; r++)
        ret *= 1.f - sigmoidf_(ifw[453 + r]) * W_read[idx * RH + r];
    float u = usage[idx], w = W_write[idx];
    usage_out[idx] = (u + w - u * w) * ret;
}

// ---------------------------------------------------------------------------
// Per-batch bitonic sort (ascending usage, index tiebreak asc) + cumprod scan
// + scatter to W_alloc
// ---------------------------------------------------------------------------
__global__ void alloc_kernel(const float* __restrict__ usage_n, float* __restrict__ Walloc) {
    __shared__ unsigned long long keys[NMEM];
    __shared__ float vals[NMEM];
    int b = blockIdx.x, t = threadIdx.x;
    float u = usage_n[b * NMEM + t];      // non-negative
    keys[t] = (((unsigned long long)__float_as_uint(u)) << 32) | (unsigned)t;
    __syncthreads();
    for (int k = 2; k <= NMEM; k <<= 1) {
        for (int j = k >> 1; j > 0; j >>= 1) {
            int p = t ^ j;
            unsigned long long mine = keys[t];
            unsigned long long other = keys[p];
            bool dirAsc = ((t & k) == 0);
            bool lower = ((t & j) == 0);
            bool takeMin = (dirAsc == lower);
            unsigned long long res;
            if (takeMin) res = (mine < other) ? mine : other;
            else         res = (mine > other) ? mine : other;
            __syncthreads();
            keys[t] = res;
            __syncthreads();
        }
    }
    float su = __uint_as_float((unsigned)(keys[t] >> 32));
    int fidx = (int)(keys[t] & 0xFFFFFFFFu);
    vals[t] = su;
    __syncthreads();
    // inclusive multiplicative scan (Hillis-Steele)
    for (int off = 1; off < NMEM; off <<= 1) {
        float prev = (t >= off) ? vals[t - off] : 1.f;
        float cur = vals[t];
        __syncthreads();
        vals[t] = cur * prev;
        __syncthreads();
    }
    float excl = (t == 0) ? 1.f : vals[t - 1];
    Walloc[b * NMEM + fidx] = (1.f - su) * excl;
}

// ---------------------------------------------------------------------------
// Write content lookup + Ww + per-batch sum(Ww)
// ---------------------------------------------------------------------------
__global__ void write_lookup_kernel(const float* __restrict__ M,
                                    float* __restrict__ Ww_out) {
    __shared__ float nk[WD];
    __shared__ float red[NMEM];
    __shared__ float sc[4];   // bwrite, alloc_g, write_g
    int b = blockIdx.x, t = threadIdx.x;
    const float* ifw = g_iface + (2 * b + 1) * IFC;
    if (t < WD) {
        float kv = ifw[260 + t];
        red[t] = kv * kv;
    }
    __syncthreads();
    if (t == 0) {
        float s = 0.f;
        for (int w = 0; w < WD; w++) s += red[w];
        sc[0] = 1.f / sqrtf(fmaxf(s, 1e-12f));
        sc[1] = 1.f + softplusf_(ifw[324]);   // b_write
        sc[2] = sigmoidf_(ifw[457]);          // alloc_g
        sc[3] = sigmoidf_(ifw[458]);          // write_g
    }
    __syncthreads();
    if (t < WD) nk[t] = ifw[260 + t] * sc[0];
    __syncthreads();

    const float* mrow = M + (b * NMEM + t) * WD;
    float dot = 0.f, nrm = 0.f;
#pragma unroll 8
    for (int w = 0; w < WD; w++) {
        float m = mrow[w];
        dot += m * nk[w];
        nrm += m * m;
    }
    float sim = dot * (1.f / sqrtf(fmaxf(nrm, 1e-12f)));
    float s = sim * sc[1];

    red[t] = s;
    __syncthreads();
    for (int off = 256; off > 0; off >>= 1) {
        if (t < off) red[t] = fmaxf(red[t], red[t + off]);
        __syncthreads();
    }
    float mxv = red[0];
    __syncthreads();
    float e = expf(s - mxv);
    red[t] = e;
    __syncthreads();
    for (int off = 256; off > 0; off >>= 1) {
        if (t < off) red[t] += red[t + off];
        __syncthreads();
    }
    float wl = e / red[0];
    __syncthreads();

    float ww = sc[3] * (sc[2] * g_Walloc[b * NMEM + t] + (1.f - sc[2]) * wl);
    Ww_out[b * NMEM + t] = ww;

    red[t] = ww;
    __syncthreads();
    for (int off = 256; off > 0; off >>= 1) {
        if (t < off) red[t] += red[t + off];
        __syncthreads();
    }
    if (t == 0) g_Wwsum[b] = red[0];
}

// ---------------------------------------------------------------------------
// Wp_n = (1 - sum(Ww)) * Wp + Ww
// ---------------------------------------------------------------------------
__global__ void wp_kernel(const float* __restrict__ Wp, const float* __restrict__ Ww,
                          float* __restrict__ Wp_out) {
    int idx = blockIdx.x * blockDim.x + threadIdx.x;
    if (idx >= BSZ * NMEM) return;
    int b = idx >> 9;
    Wp_out[idx] = (1.f - g_Wwsum[b]) * Wp[idx] + Ww[idx];
}

// ---------------------------------------------------------------------------
// M_n = M * (1 - ww*erase) + ww*write_v
// ---------------------------------------------------------------------------
__global__ void mnew_kernel(const float* __restrict__ M, const float* __restrict__ Ww,
                            float* __restrict__ Mn) {
    int idx = blockIdx.x * blockDim.x + threadIdx.x;
    if (idx >= BSZ * NMEM * WD) return;
    int b = idx >> 15;
    int n = (idx >> 6) & 511;
    int w = idx & 63;
    const float* ifw = g_iface + (2 * b + 1) * IFC;
    float e = sigmoidf_(ifw[325 + w]);
    float v = ifw[389 + w];
    float ww = Ww[b * NMEM + n];
    Mn[idx] = M[idx] * (1.f - ww * e) + ww * v;
}

// ---------------------------------------------------------------------------
// Link update + fused fwd/bwd partial reductions, 64x64 tiles
// grid (64 tiles, 64 batches), block 256
// ---------------------------------------------------------------------------
__global__ void link_kernel(const float* __restrict__ L, const float* __restrict__ Ww,
                            const float* __restrict__ Wp, const float* __restrict__ Wr,
                            float* __restrict__ Ln_out) {
    __shared__ float Ln_s[64][65];
    __shared__ float Wwi[64], Wwj[64], Wpj[64];
    __shared__ float Wri[64][4], Wrj[64][4];
    int b = blockIdx.y;
    int it = blockIdx.x >> 3, jt = blockIdx.x & 7;
    int i0 = it * 64, j0 = jt * 64;
    int t = threadIdx.x;
    if (t < 64) {
        Wwi[t] = Ww[b * NMEM + i0 + t];
        Wwj[t] = Ww[b * NMEM + j0 + t];
        Wpj[t] = Wp[b * NMEM + j0 + t];
    }
    {
        int n = t >> 2, r = t & 3;
        Wri[n][r] = Wr[(b * NMEM + i0 + n) * RH + r];
        Wrj[n][r] = Wr[(b * NMEM + j0 + n) * RH + r];
    }
    __syncthreads();
#pragma unroll
    for (int k = 0; k < 16; k++) {
        int e = t + k * 256;
        int il = e >> 6, jl = e & 63;
        long gidx = ((long)(b * NMEM + i0 + il)) * NMEM + j0 + jl;
        float l = L[gidx];
        float ln = (1.f - Wwi[il] - Wwj[jl]) * l + Wwi[il] * Wpj[jl];
        if (i0 + il == j0 + jl) ln = 0.f;
        Ln_s[il][jl] = ln;
        Ln_out[gidx] = ln;
    }
    __syncthreads();
    {
        int il = t >> 2, r = t & 3;
        float accF = 0.f, accB = 0.f;
#pragma unroll
        for (int c = 0; c < 64; c++) {
            accF += Ln_s[il][c] * Wrj[c][r];   // fwd: row-reduction over j
            accB += Ln_s[c][il] * Wri[c][r];   // bwd: col-reduction over i
        }
        g_fwdpart[((b * 8 + jt) * NMEM + i0 + il) * RH + r] = accF;
        g_bwdpart[((b * 8 + it) * NMEM + j0 + il) * RH + r] = accB;
    }
}

__global__ void reduce_fb_kernel() {
    int idx = blockIdx.x * blockDim.x + threadIdx.x;
    if (idx >= BSZ * NMEM * RH) return;
    int b = idx >> 11;
    int nr = idx & 2047;
    float f = 0.f, bd = 0.f;
#pragma unroll
    for (int c = 0; c < 8; c++) {
        f  += g_fwdpart[(b * 8 + c) * 2048 + nr];
        bd += g_bwdpart[(b * 8 + c) * 2048 + nr];
    }
    g_fwd[idx] = f;
    g_bwd[idx] = bd;
}

// ---------------------------------------------------------------------------
// Read content lookup (4 heads) + mode-mix -> Wr_n
// ---------------------------------------------------------------------------
__global__ void read_kernel(const float* __restrict__ Mn, float* __restrict__ Wr_out) {
    __shared__ float nk[RH][WD];
    __shared__ float br[RH];
    __shared__ float m0[RH], m1[RH], m2[RH];
    __shared__ float red[NMEM];
    int b = blockIdx.x, t = threadIdx.x;
    const float* ifr = g_iface + (2 * b) * IFC;
    if (t < RH * WD) {
        int r = t >> 6, w = t & 63;
        nk[r][w] = ifr[r * WD + w];
    }
    if (t < RH) {
        br[t] = 1.f + softplusf_(ifr[256 + t]);
        float a = ifr[459 + t], bb = ifr[463 + t], c = ifr[467 + t];
        float mx = fmaxf(a, fmaxf(bb, c));
        float ea = expf(a - mx), eb = expf(bb - mx), ec = expf(c - mx);
        float s = ea + eb + ec;
        m0[t] = ea / s; m1[t] = eb / s; m2[t] = ec / s;
    }
    __syncthreads();
    if (t < RH) {
        float s = 0.f;
        for (int w = 0; w < WD; w++) { float v = nk[t][w]; s += v * v; }
        float rn = 1.f / sqrtf(fmaxf(s, 1e-12f));
        for (int w = 0; w < WD; w++) nk[t][w] *= rn;
    }
    __syncthreads();

    const float* mrow = Mn + (b * NMEM + t) * WD;
    float d[RH] = {0.f, 0.f, 0.f, 0.f};
    float nrm = 0.f;
#pragma unroll 8
    for (int w = 0; w < WD; w++) {
        float m = mrow[w];
        nrm += m * m;
        d[0] += m * nk[0][w];
        d[1] += m * nk[1][w];
        d[2] += m * nk[2][w];
        d[3] += m * nk[3][w];
    }
    float rn = 1.f / sqrtf(fmaxf(nrm, 1e-12f));
    float wl[RH];
#pragma unroll
    for (int r = 0; r < RH; r++) {
        float s = d[r] * rn * br[r];
        red[t] = s;
        __syncthreads();
        for (int off = 256; off > 0; off >>= 1) {
            if (t < off) red[t] = fmaxf(red[t], red[t + off]);
            __syncthreads();
        }
        float mxv = red[0];
        __syncthreads();
        float e = expf(s - mxv);
        red[t] = e;
        __syncthreads();
        for (int off = 256; off > 0; off >>= 1) {
            if (t < off) red[t] += red[t + off];
            __syncthreads();
        }
        wl[r] = e / red[0];
        __syncthreads();
    }
#pragma unroll
    for (int r = 0; r < RH; r++) {
        int gi = (b * NMEM + t) * RH + r;
        Wr_out[gi] = m0[r] * g_bwd[gi] + m1[r] * wl[r] + m2[r] * g_fwd[gi];
    }
}

// ---------------------------------------------------------------------------
// read_v[b,r,w] = sum_n Mn[b,n,w] * Wr_n[b,n,r] ; y = read_v @ W_read_out
// block = 256 threads per batch
// ---------------------------------------------------------------------------
__global__ void readv_kernel(const float* __restrict__ Mn, const float* __restrict__ Wr,
                             const float* __restrict__ Wro, float* __restrict__ y_out) {
    __shared__ float Ms[64][64];
    __shared__ float Ws[64][4];
    __shared__ float rv[256];
    int b = blockIdx.x, t = threadIdx.x;
    int r = t >> 6, w = t & 63;
    float acc = 0.f;
    for (int n0 = 0; n0 < NMEM; n0 += 64) {
#pragma unroll
        for (int k = 0; k < 16; k++) {
            int e = t + k * 256;
            int nn = e >> 6, ww = e & 63;
            Ms[nn][ww] = Mn[(b * NMEM + n0 + nn) * WD + ww];
        }
        {
            int nn = t >> 2, rr = t & 3;
            Ws[nn][rr] = Wr[(b * NMEM + n0 + nn) * RH + rr];
        }
        __syncthreads();
#pragma unroll
        for (int nn = 0; nn < 64; nn++) acc += Ms[nn][w] * Ws[nn][r];
        __syncthreads();
    }
    rv[t] = acc;   // layout r*64+w == t
    __syncthreads();
    float ya = 0.f;
#pragma unroll 8
    for (int k = 0; k < 256; k++) ya += rv[k] * Wro[k * OUTD + t];
    y_out[b * OUTD + t] = ya;
}

// ---------------------------------------------------------------------------
extern "C" void kernel_launch(void* const* d_in, const int* in_sizes, int n_in,
                              void* d_out, int out_size) {
    const float* inputs   = (const float*)d_in[0];
    const float* M        = (const float*)d_in[1];
    const float* usage    = (const float*)d_in[2];
    const float* L        = (const float*)d_in[3];
    const float* Wp       = (const float*)d_in[4];
    const float* W_read   = (const float*)d_in[5];
    const float* W_write  = (const float*)d_in[6];
    const float* h_ctrl   = (const float*)d_in[7];
    const float* W_iface  = (const float*)d_in[8];
    const float* W_rdout  = (const float*)d_in[9];
    const float* gru_k    = (const float*)d_in[10];
    const float* gru_rk   = (const float*)d_in[11];
    const float* gru_b    = (const float*)d_in[12];

    float* out = (float*)d_out;
    float* o_y    = out + OFF_Y;
    float* o_mn   = out + OFF_MN;
    float* o_use  = out + OFF_USAGE;
    float* o_ln   = out + OFF_LN;
    float* o_wp   = out + OFF_WP;
    float* o_wr   = out + OFF_WR;
    float* o_ww   = out + OFF_WW;
    float* o_hc   = out + OFF_HC;

    float *d_mx, *d_mh, *d_iface, *d_walloc;
    cudaGetSymbolAddress((void**)&d_mx, g_mx);
    cudaGetSymbolAddress((void**)&d_mh, g_mh);
    cudaGetSymbolAddress((void**)&d_iface, g_iface);
    cudaGetSymbolAddress((void**)&d_walloc, g_Walloc);

    dim3 b32(32, 32);
    // 1) GRU mats: mx = X @ gru_kernel + bias0 ; mh = H @ gru_rkernel + bias1
    sgemm_bias<<<dim3((G3 + 31) / 32, 4), b32>>>(inputs, gru_k, gru_b, d_mx, 128, G3, IND);
    sgemm_bias<<<dim3((G3 + 31) / 32, 4), b32>>>(h_ctrl, gru_rk, gru_b + G3, d_mh, 128, G3, CD);
    // 2) combine -> hc (output + controller state)
    gru_combine<<<(128 * CD + 255) / 256, 256>>>(h_ctrl, o_hc);
    // 3) interface = hc @ W_interface
    sgemm_bias<<<dim3((IFC + 31) / 32, 4), b32>>>(o_hc, W_iface, nullptr, d_iface, 128, IFC, CD);
    // 4) usage_n
    usage_kernel<<<(BSZ * NMEM + 255) / 256, 256>>>(W_read, W_write, usage, o_use);
    // 5) sort + allocation weighting
    alloc_kernel<<<BSZ, NMEM>>>(o_use, d_walloc);
    // 6) write lookup + Ww
    write_lookup_kernel<<<BSZ, NMEM>>>(M, o_ww);
    // 7) precedence update
    wp_kernel<<<(BSZ * NMEM + 255) / 256, 256>>>(Wp, o_ww, o_wp);
    // 8) memory write
    mnew_kernel<<<(BSZ * NMEM * WD + 255) / 256, 256>>>(M, o_ww, o_mn);
    // 9) link update fused with fwd/bwd partials
    link_kernel<<<dim3(64, BSZ), 256>>>(L, o_ww, Wp, W_read, o_ln);
    // 10) reduce fwd/bwd partials
    reduce_fb_kernel<<<(BSZ * NMEM * RH + 255) / 256, 256>>>();
    // 11) read lookup + mode mix -> Wr_n
    read_kernel<<<BSZ, NMEM>>>(o_mn, o_wr);
    // 12) read vectors + output projection
    readv_kernel<<<BSZ, 256>>>(o_mn, o_wr, W_rdout, o_y);
}

// round 3
// speedup vs baseline: 1.5051x; 1.5051x over previous
#include <cuda_runtime.h>
#include <math.h>

// Problem dims
#define BSZ   64
#define NMEM  512
#define WD    64
#define RH    4
#define OUTD  256
#define IND   256
#define IFC   471     // interface size
#define CD    727     // controller dim
#define G3    2181    // 3*CD

// Output layout offsets (concatenated flattened tuple, f32)
#define OFF_Y      0
#define OFF_MN     16384
#define OFF_USAGE  2113536
#define OFF_LN     2146304
#define OFF_WP     18923520
#define OFF_WR     18956288
#define OFF_WW     19087360
#define OFF_HC     19120128

// Scratch (no cudaMalloc allowed)
__device__ float g_mx[128 * G3];
__device__ float g_mh[128 * G3];
__device__ float g_iface[128 * IFC];
__device__ float g_fwdpart[BSZ * 8 * NMEM * RH];
__device__ float g_bwdpart[BSZ * 8 * NMEM * RH];

__device__ __forceinline__ float sigmoidf_(float x) { return 1.f / (1.f + expf(-x)); }
__device__ __forceinline__ float softplusf_(float x) { return fmaxf(x, 0.f) + log1pf(expf(-fabsf(x))); }

// ---------------------------------------------------------------------------
// Register-tiled GEMM body: C[M,N] = A[M,K] @ B[K,N] (+bias).
// Block tile 32x32, 128 threads, per-thread 2x4, K-tiles of 32.
// M is always 128 (grid.y = 4 exact). N,K arbitrary.
// ---------------------------------------------------------------------------
__device__ __forceinline__ void gemm_body(const float* __restrict__ A,
                                          const float* __restrict__ B,
                                          const float* __restrict__ bias,
                                          float* __restrict__ C,
                                          int N, int K) {
    __shared__ __align__(16) float Ast[32][34];   // transposed A tile, padded
    __shared__ __align__(16) float Bs[32][32];
    int t = threadIdx.x;            // 128 threads
    int m0 = blockIdx.y * 32;
    int n0 = blockIdx.x * 32;
    if (n0 >= N) return;
    int tx = t & 7;                 // col group (4 cols)
    int ty = t >> 3;                // row group (2 rows)
    float acc[2][4] = {{0.f,0.f,0.f,0.f},{0.f,0.f,0.f,0.f}};

    for (int k0 = 0; k0 < K; k0 += 32) {
#pragma unroll
        for (int i = 0; i < 8; i++) {
            int e = t + i * 128;
            int k = e & 31, m = e >> 5;
            float v = 0.f;
            if (k0 + k < K) v = A[(m0 + m) * K + k0 + k];
            Ast[k][m] = v;
        }
#pragma unroll
        for (int i = 0; i < 8; i++) {
            int e = t + i * 128;
            int c = e & 31, k = e >> 5;
            float v = 0.f;
            if (k0 + k < K && n0 + c < N) v = B[(k0 + k) * N + n0 + c];
            Bs[k][c] = v;
        }
        __syncthreads();
#pragma unroll
        for (int kk = 0; kk < 32; kk++) {
            float2 a2 = *(const float2*)&Ast[kk][ty * 2];
            float4 b4 = *(const float4*)&Bs[kk][tx * 4];
            acc[0][0] += a2.x * b4.x; acc[0][1] += a2.x * b4.y;
            acc[0][2] += a2.x * b4.z; acc[0][3] += a2.x * b4.w;
            acc[1][0] += a2.y * b4.x; acc[1][1] += a2.y * b4.y;
            acc[1][2] += a2.y * b4.z; acc[1][3] += a2.y * b4.w;
        }
        __syncthreads();
    }
#pragma unroll
    for (int i = 0; i < 2; i++) {
        int row = m0 + ty * 2 + i;
#pragma unroll
        for (int j = 0; j < 4; j++) {
            int col = n0 + tx * 4 + j;
            if (col < N) {
                float v = acc[i][j];
                if (bias) v += bias[col];
                C[row * N + col] = v;
            }
        }
    }
}

// Dual launch: z=0 -> mx = X @ gru_k + b0 ; z=1 -> mh = H @ gru_rk + b1
__global__ void gemm_gru(const float* __restrict__ X, const float* __restrict__ H,
                         const float* __restrict__ gk, const float* __restrict__ grk,
                         const float* __restrict__ gb) {
    if (blockIdx.z == 0) gemm_body(X, gk, gb, g_mx, G3, IND);
    else                 gemm_body(H, grk, gb + G3, g_mh, G3, CD);
}

__global__ void gemm_iface(const float* __restrict__ hc, const float* __restrict__ Wif) {
    gemm_body(hc, Wif, nullptr, g_iface, IFC, CD);
}

// ---------------------------------------------------------------------------
// GRU combine: c = z*h + (1-z)*gelu(xh + r*rh)
// ---------------------------------------------------------------------------
__global__ void gru_combine(const float* __restrict__ h, float* __restrict__ hc_out) {
    int idx = blockIdx.x * blockDim.x + threadIdx.x;
    if (idx >= 128 * CD) return;
    int row = idx / CD, j = idx % CD;
    const float* mx = g_mx + row * G3;
    const float* mh = g_mh + row * G3;
    float z = sigmoidf_(mx[j] + mh[j]);
    float r = sigmoidf_(mx[CD + j] + mh[CD + j]);
    float hin = mx[2 * CD + j] + r * mh[2 * CD + j];
    float hh = hin * normcdff(hin);   // exact gelu
    float hv = h[idx];
    hc_out[idx] = z * hv + (1.f - z) * hh;
}

// ---------------------------------------------------------------------------
// Fused per-batch memory update:
//   usage_n -> bitonic sort + cumprod scan -> W_alloc -> write content lookup
//   -> Ww -> Wp_n -> M_n
// 64 blocks x 512 threads
// ---------------------------------------------------------------------------
__global__ void memupdate_kernel(const float* __restrict__ W_read,
                                 const float* __restrict__ W_write,
                                 const float* __restrict__ usage,
                                 const float* __restrict__ M,
                                 const float* __restrict__ Wp,
                                 float* __restrict__ usage_out,
                                 float* __restrict__ Ww_out,
                                 float* __restrict__ Wp_out,
                                 float* __restrict__ Mn_out) {
    __shared__ unsigned long long keys[NMEM];
    __shared__ float vals[NMEM];
    __shared__ float red[NMEM];
    __shared__ float wall[NMEM];
    __shared__ float wws[NMEM];
    __shared__ float nk[WD];
    __shared__ __align__(16) float es[WD];
    __shared__ __align__(16) float vs[WD];
    __shared__ float sc[4];
    int b = blockIdx.x, t = threadIdx.x;
    const float* ifw = g_iface + (2 * b + 1) * IFC;

    // --- usage_n ---
    float ret = 1.f;
#pragma unroll
    for (int r = 0; r < RH; r++)
        ret *= 1.f - sigmoidf_(ifw[453 + r]) * W_read[(b * NMEM + t) * RH + r];
    float u = usage[b * NMEM + t], w = W_write[b * NMEM + t];
    float un = (u + w - u * w) * ret;
    usage_out[b * NMEM + t] = un;
    keys[t] = (((unsigned long long)__float_as_uint(un)) << 32) | (unsigned)t;
    // scalar prep (overlap with sort barriers)
    if (t < WD) { es[t] = sigmoidf_(ifw[325 + t]); vs[t] = ifw[389 + t];
                  float kv = ifw[260 + t]; red[t] = kv * kv; }
    __syncthreads();
    if (t == 0) {
        float s = 0.f;
        for (int ww2 = 0; ww2 < WD; ww2++) s += red[ww2];
        sc[0] = 1.f / sqrtf(fmaxf(s, 1e-12f));
        sc[1] = 1.f + softplusf_(ifw[324]);   // b_write
        sc[2] = sigmoidf_(ifw[457]);          // alloc_g
        sc[3] = sigmoidf_(ifw[458]);          // write_g
    }
    __syncthreads();
    if (t < WD) nk[t] = ifw[260 + t] * sc[0];

    // --- bitonic sort ascending (usage asc, index asc tiebreak) ---
    for (int k = 2; k <= NMEM; k <<= 1) {
        for (int j = k >> 1; j > 0; j >>= 1) {
            int p = t ^ j;
            unsigned long long mine = keys[t];
            unsigned long long other = keys[p];
            bool dirAsc = ((t & k) == 0);
            bool lower = ((t & j) == 0);
            bool takeMin = (dirAsc == lower);
            unsigned long long res = takeMin ? (mine < other ? mine : other)
                                             : (mine > other ? mine : other);
            __syncthreads();
            keys[t] = res;
            __syncthreads();
        }
    }
    float su = __uint_as_float((unsigned)(keys[t] >> 32));
    int fidx = (int)(keys[t] & 0xFFFFFFFFu);
    vals[t] = su;
    __syncthreads();
    // inclusive multiplicative scan
    for (int off = 1; off < NMEM; off <<= 1) {
        float prev = (t >= off) ? vals[t - off] : 1.f;
        float cur = vals[t];
        __syncthreads();
        vals[t] = cur * prev;
        __syncthreads();
    }
    float excl = (t == 0) ? 1.f : vals[t - 1];
    wall[fidx] = (1.f - su) * excl;
    __syncthreads();

    // --- write content lookup ---
    const float* mrow = M + (b * NMEM + t) * WD;
    float dot = 0.f, nrm = 0.f;
#pragma unroll 8
    for (int ww2 = 0; ww2 < WD; ww2++) {
        float m = mrow[ww2];
        dot += m * nk[ww2];
        nrm += m * m;
    }
    float s = dot * (1.f / sqrtf(fmaxf(nrm, 1e-12f))) * sc[1];
    red[t] = s;
    __syncthreads();
    for (int off = 256; off > 0; off >>= 1) {
        if (t < off) red[t] = fmaxf(red[t], red[t + off]);
        __syncthreads();
    }
    float mxv = red[0];
    __syncthreads();
    float e = expf(s - mxv);
    red[t] = e;
    __syncthreads();
    for (int off = 256; off > 0; off >>= 1) {
        if (t < off) red[t] += red[t + off];
        __syncthreads();
    }
    float wl = e / red[0];
    __syncthreads();

    float ww = sc[3] * (sc[2] * wall[t] + (1.f - sc[2]) * wl);
    Ww_out[b * NMEM + t] = ww;
    wws[t] = ww;
    red[t] = ww;
    __syncthreads();
    for (int off = 256; off > 0; off >>= 1) {
        if (t < off) red[t] += red[t + off];
        __syncthreads();
    }
    float wsum = red[0];
    // --- precedence ---
    Wp_out[b * NMEM + t] = (1.f - wsum) * Wp[b * NMEM + t] + ww;

    // --- M_n (float4, coalesced) ---
    const float4* M4 = (const float4*)(M + b * NMEM * WD);
    float4* Mn4 = (float4*)(Mn_out + b * NMEM * WD);
    const float4* es4 = (const float4*)es;
    const float4* vs4 = (const float4*)vs;
#pragma unroll
    for (int i = 0; i < 16; i++) {
        int idx4 = t + i * NMEM;       // 8192 float4 per batch
        int n = idx4 >> 4, w4 = idx4 & 15;
        float wwn = wws[n];
        float4 m4 = M4[idx4];
        float4 e4 = es4[w4];
        float4 v4 = vs4[w4];
        float4 o;
        o.x = m4.x * (1.f - wwn * e4.x) + wwn * v4.x;
        o.y = m4.y * (1.f - wwn * e4.y) + wwn * v4.y;
        o.z = m4.z * (1.f - wwn * e4.z) + wwn * v4.z;
        o.w = m4.w * (1.f - wwn * e4.w) + wwn * v4.w;
        Mn4[idx4] = o;
    }
}

// ---------------------------------------------------------------------------
// Link update + fused fwd/bwd partial reductions, 64x64 tiles, float4 I/O.
// grid (64 tiles, 64 batches), block 256
// ---------------------------------------------------------------------------
__global__ void link_kernel(const float* __restrict__ L, const float* __restrict__ Ww,
                            const float* __restrict__ Wp, const float* __restrict__ Wr,
                            float* __restrict__ Ln_out) {
    __shared__ __align__(16) float Ln_s[64][68];
    __shared__ float Wwi[64], Wwj[64], Wpj[64];
    __shared__ float Wri[64][4], Wrj[64][4];
    int b = blockIdx.y;
    int it = blockIdx.x >> 3, jt = blockIdx.x & 7;
    int i0 = it * 64, j0 = jt * 64;
    int t = threadIdx.x;
    if (t < 64) {
        Wwi[t] = Ww[b * NMEM + i0 + t];
        Wwj[t] = Ww[b * NMEM + j0 + t];
        Wpj[t] = Wp[b * NMEM + j0 + t];
    }
    {
        int n = t >> 2, r = t & 3;
        Wri[n][r] = Wr[(b * NMEM + i0 + n) * RH + r];
        Wrj[n][r] = Wr[(b * NMEM + j0 + n) * RH + r];
    }
    __syncthreads();
#pragma unroll
    for (int k = 0; k < 4; k++) {
        int e4 = t + k * 256;               // 1024 float4 in tile
        int il = e4 >> 4, j4 = (e4 & 15) * 4;
        long gidx = ((long)(b * NMEM + i0 + il)) * NMEM + j0 + j4;
        float4 l4 = *(const float4*)(L + gidx);
        float wwi = Wwi[il];
        float4 ln;
        ln.x = (1.f - wwi - Wwj[j4 + 0]) * l4.x + wwi * Wpj[j4 + 0];
        ln.y = (1.f - wwi - Wwj[j4 + 1]) * l4.y + wwi * Wpj[j4 + 1];
        ln.z = (1.f - wwi - Wwj[j4 + 2]) * l4.z + wwi * Wpj[j4 + 2];
        ln.w = (1.f - wwi - Wwj[j4 + 3]) * l4.w + wwi * Wpj[j4 + 3];
        if (it == jt) {
            if (il == j4 + 0) ln.x = 0.f;
            if (il == j4 + 1) ln.y = 0.f;
            if (il == j4 + 2) ln.z = 0.f;
            if (il == j4 + 3) ln.w = 0.f;
        }
        *(float4*)&Ln_s[il][j4] = ln;
        *(float4*)(Ln_out + gidx) = ln;
    }
    __syncthreads();
    {
        int il = t >> 2, r = t & 3;
        float accF = 0.f, accB = 0.f;
#pragma unroll
        for (int c = 0; c < 64; c++) {
            accF += Ln_s[il][c] * Wrj[c][r];   // fwd: row-reduction over j
            accB += Ln_s[c][il] * Wri[c][r];   // bwd: col-reduction over i
        }
        g_fwdpart[((b * 8 + jt) * NMEM + i0 + il) * RH + r] = accF;
        g_bwdpart[((b * 8 + it) * NMEM + j0 + il) * RH + r] = accB;
    }
}

// ---------------------------------------------------------------------------
// Fused: partial reduce + read content lookup + mode mix -> Wr_n
//        + read vectors + output projection. 64 blocks x 512 threads.
// ---------------------------------------------------------------------------
__global__ void read_fused_kernel(const float* __restrict__ Mn,
                                  const float* __restrict__ Wro,
                                  float* __restrict__ Wr_out,
                                  float* __restrict__ y_out) {
    __shared__ float fwd_s[NMEM * RH];   // 8KB
    __shared__ float bwd_s[NMEM * RH];   // 8KB
    __shared__ float Wrs[NMEM][RH];      // 8KB
    __shared__ float nk[RH][WD];
    __shared__ float br[RH];
    __shared__ float m0s[RH], m1s[RH], m2s[RH];
    __shared__ float red[NMEM];
    __shared__ float rv[256];
    int b = blockIdx.x, t = threadIdx.x;
    const float* ifr = g_iface + (2 * b) * IFC;

    // reduce 8 partial tiles
#pragma unroll
    for (int i = 0; i < 4; i++) {
        int idx = t + i * 512;           // 2048 (n,r)
        float f = 0.f, bd = 0.f;
#pragma unroll
        for (int c = 0; c < 8; c++) {
            f  += g_fwdpart[(b * 8 + c) * (NMEM * RH) + idx];
            bd += g_bwdpart[(b * 8 + c) * (NMEM * RH) + idx];
        }
        fwd_s[idx] = f;
        bwd_s[idx] = bd;
    }
    if (t < RH * WD) {
        int r = t >> 6, w = t & 63;
        nk[r][w] = ifr[r * WD + w];
    }
    if (t >= 256 && t < 256 + RH) {
        int r = t - 256;
        br[r] = 1.f + softplusf_(ifr[256 + r]);
        float a = ifr[459 + r], bb = ifr[463 + r], c = ifr[467 + r];
        float mx = fmaxf(a, fmaxf(bb, c));
        float ea = expf(a - mx), eb = expf(bb - mx), ec = expf(c - mx);
        float s = ea + eb + ec;
        m0s[r] = ea / s; m1s[r] = eb / s; m2s[r] = ec / s;
    }
    __syncthreads();
    if (t < RH) {
        float s = 0.f;
        for (int w = 0; w < WD; w++) { float v = nk[t][w]; s += v * v; }
        float rn = 1.f / sqrtf(fmaxf(s, 1e-12f));
        for (int w = 0; w < WD; w++) nk[t][w] *= rn;
    }
    __syncthreads();

    // content lookup (4 heads)
    const float* mrow = Mn + (b * NMEM + t) * WD;
    float d[RH] = {0.f, 0.f, 0.f, 0.f};
    float nrm = 0.f;
#pragma unroll 8
    for (int w = 0; w < WD; w++) {
        float m = mrow[w];
        nrm += m * m;
        d[0] += m * nk[0][w];
        d[1] += m * nk[1][w];
        d[2] += m * nk[2][w];
        d[3] += m * nk[3][w];
    }
    float rn = 1.f / sqrtf(fmaxf(nrm, 1e-12f));
    float wl[RH];
#pragma unroll
    for (int r = 0; r < RH; r++) {
        float s = d[r] * rn * br[r];
        red[t] = s;
        __syncthreads();
        for (int off = 256; off > 0; off >>= 1) {
            if (t < off) red[t] = fmaxf(red[t], red[t + off]);
            __syncthreads();
        }
        float mxv = red[0];
        __syncthreads();
        float e = expf(s - mxv);
        red[t] = e;
        __syncthreads();
        for (int off = 256; off > 0; off >>= 1) {
            if (t < off) red[t] += red[t + off];
            __syncthreads();
        }
        wl[r] = e / red[0];
        __syncthreads();
    }
#pragma unroll
    for (int r = 0; r < RH; r++) {
        float v = m0s[r] * bwd_s[t * RH + r] + m1s[r] * wl[r] + m2s[r] * fwd_s[t * RH + r];
        Wr_out[(b * NMEM + t) * RH + r] = v;
        Wrs[t][r] = v;
    }
    __syncthreads();

    // read vectors: rv[r*64+w] = sum_n Mn[n,w] * Wr[n,r]
    if (t < 256) {
        int r = t >> 6, w = t & 63;
        float acc = 0.f;
#pragma unroll 8
        for (int n = 0; n < NMEM; n++)
            acc += Mn[(b * NMEM + n) * WD + w] * Wrs[n][r];
        rv[t] = acc;
    }
    __syncthreads();
    // y = rv @ W_read_out
    if (t < 256) {
        float ya = 0.f;
#pragma unroll 8
        for (int k = 0; k < 256; k++) ya += rv[k] * Wro[k * OUTD + t];
        y_out[b * OUTD + t] = ya;
    }
}

// ---------------------------------------------------------------------------
extern "C" void kernel_launch(void* const* d_in, const int* in_sizes, int n_in,
                              void* d_out, int out_size) {
    const float* inputs   = (const float*)d_in[0];
    const float* M        = (const float*)d_in[1];
    const float* usage    = (const float*)d_in[2];
    const float* L        = (const float*)d_in[3];
    const float* Wp       = (const float*)d_in[4];
    const float* W_read   = (const float*)d_in[5];
    const float* W_write  = (const float*)d_in[6];
    const float* h_ctrl   = (const float*)d_in[7];
    const float* W_iface  = (const float*)d_in[8];
    const float* W_rdout  = (const float*)d_in[9];
    const float* gru_k    = (const float*)d_in[10];
    const float* gru_rk   = (const float*)d_in[11];
    const float* gru_b    = (const float*)d_in[12];

    float* out = (float*)d_out;
    float* o_y    = out + OFF_Y;
    float* o_mn   = out + OFF_MN;
    float* o_use  = out + OFF_USAGE;
    float* o_ln   = out + OFF_LN;
    float* o_wp   = out + OFF_WP;
    float* o_wr   = out + OFF_WR;
    float* o_ww   = out + OFF_WW;
    float* o_hc   = out + OFF_HC;

    // 1) GRU mats mx & mh in one launch (independent, z selects)
    gemm_gru<<<dim3((G3 + 31) / 32, 4, 2), 128>>>(inputs, h_ctrl, gru_k, gru_rk, gru_b);
    // 2) combine -> hc
    gru_combine<<<(128 * CD + 255) / 256, 256>>>(h_ctrl, o_hc);
    // 3) interface = hc @ W_interface
    gemm_iface<<<dim3((IFC + 31) / 32, 4), 128>>>(o_hc, W_iface);
    // 4) fused usage + sort/alloc + write lookup + Ww + Wp + M_n
    memupdate_kernel<<<BSZ, NMEM>>>(W_read, W_write, usage, M, Wp,
                                    o_use, o_ww, o_wp, o_mn);
    // 5) link update fused with fwd/bwd partials
    link_kernel<<<dim3(64, BSZ), 256>>>(L, o_ww, Wp, W_read, o_ln);
    // 6) fused reduce + read lookup + Wr + read vectors + y
    read_fused_kernel<<<BSZ, NMEM>>>(o_mn, W_rdout, o_wr, o_y);
}

// round 4
// speedup vs baseline: 1.7539x; 1.1654x over previous
#include <cuda_runtime.h>
#include <math.h>

// Problem dims
#define BSZ   64
#define NMEM  512
#define WD    64
#define RH    4
#define OUTD  256
#define IND   256
#define IFC   471     // interface size
#define CD    727     // controller dim
#define G3    2181    // 3*CD

// Output layout offsets (concatenated flattened tuple, f32)
#define OFF_Y      0
#define OFF_MN     16384
#define OFF_USAGE  2113536
#define OFF_LN     2146304
#define OFF_WP     18923520
#define OFF_WR     18956288
#define OFF_WW     19087360
#define OFF_HC     19120128

// Scratch (no cudaMalloc allowed)
__device__ float g_mx[128 * G3];
__device__ float g_mh[128 * G3];
__device__ float g_iface[128 * IFC];
__device__ __align__(16) float g_fwdpart[BSZ * 8 * NMEM * RH];
__device__ __align__(16) float g_bwdpart[BSZ * 8 * NMEM * RH];

__device__ __forceinline__ float sigmoidf_(float x) { return 1.f / (1.f + expf(-x)); }
__device__ __forceinline__ float softplusf_(float x) { return fmaxf(x, 0.f) + log1pf(expf(-fabsf(x))); }

// Block-wide reductions for 512 threads: shuffle within warp + 16-slot shared.
// 2 barriers each (first barrier protects sb reuse across calls).
__device__ __forceinline__ float blk_red_max(float v, float* sb, int t) {
#pragma unroll
    for (int o = 16; o; o >>= 1) v = fmaxf(v, __shfl_xor_sync(0xffffffffu, v, o));
    __syncthreads();
    if ((t & 31) == 0) sb[t >> 5] = v;
    __syncthreads();
    float r = sb[0];
#pragma unroll
    for (int i = 1; i < 16; i++) r = fmaxf(r, sb[i]);
    return r;
}
__device__ __forceinline__ float blk_red_sum(float v, float* sb, int t) {
#pragma unroll
    for (int o = 16; o; o >>= 1) v += __shfl_xor_sync(0xffffffffu, v, o);
    __syncthreads();
    if ((t & 31) == 0) sb[t >> 5] = v;
    __syncthreads();
    float r = 0.f;
#pragma unroll
    for (int i = 0; i < 16; i++) r += sb[i];
    return r;
}

// ---------------------------------------------------------------------------
// Register-tiled GEMM body: C[M,N] = A[M,K] @ B[K,N] (+bias).
// Block tile 32x32, 128 threads, per-thread 2x4, K-tiles of 32.
// ---------------------------------------------------------------------------
__device__ __forceinline__ void gemm_body(const float* __restrict__ A,
                                          const float* __restrict__ B,
                                          const float* __restrict__ bias,
                                          float* __restrict__ C,
                                          int N, int K) {
    __shared__ __align__(16) float Ast[32][34];   // transposed A tile, padded
    __shared__ __align__(16) float Bs[32][32];
    int t = threadIdx.x;            // 128 threads
    int m0 = blockIdx.y * 32;
    int n0 = blockIdx.x * 32;
    if (n0 >= N) return;
    int tx = t & 7;                 // col group (4 cols)
    int ty = t >> 3;                // row group (2 rows)
    float acc[2][4] = {{0.f,0.f,0.f,0.f},{0.f,0.f,0.f,0.f}};

    for (int k0 = 0; k0 < K; k0 += 32) {
#pragma unroll
        for (int i = 0; i < 8; i++) {
            int e = t + i * 128;
            int k = e & 31, m = e >> 5;
            float v = 0.f;
            if (k0 + k < K) v = A[(m0 + m) * K + k0 + k];
            Ast[k][m] = v;
        }
#pragma unroll
        for (int i = 0; i < 8; i++) {
            int e = t + i * 128;
            int c = e & 31, k = e >> 5;
            float v = 0.f;
            if (k0 + k < K && n0 + c < N) v = B[(k0 + k) * N + n0 + c];
            Bs[k][c] = v;
        }
        __syncthreads();
#pragma unroll
        for (int kk = 0; kk < 32; kk++) {
            float2 a2 = *(const float2*)&Ast[kk][ty * 2];
            float4 b4 = *(const float4*)&Bs[kk][tx * 4];
            acc[0][0] += a2.x * b4.x; acc[0][1] += a2.x * b4.y;
            acc[0][2] += a2.x * b4.z; acc[0][3] += a2.x * b4.w;
            acc[1][0] += a2.y * b4.x; acc[1][1] += a2.y * b4.y;
            acc[1][2] += a2.y * b4.z; acc[1][3] += a2.y * b4.w;
        }
        __syncthreads();
    }
#pragma unroll
    for (int i = 0; i < 2; i++) {
        int row = m0 + ty * 2 + i;
#pragma unroll
        for (int j = 0; j < 4; j++) {
            int col = n0 + tx * 4 + j;
            if (col < N) {
                float v = acc[i][j];
                if (bias) v += bias[col];
                C[row * N + col] = v;
            }
        }
    }
}

// Dual launch: z=0 -> mx = X @ gru_k + b0 ; z=1 -> mh = H @ gru_rk + b1
__global__ void gemm_gru(const float* __restrict__ X, const float* __restrict__ H,
                         const float* __restrict__ gk, const float* __restrict__ grk,
                         const float* __restrict__ gb) {
    if (blockIdx.z == 0) gemm_body(X, gk, gb, g_mx, G3, IND);
    else                 gemm_body(H, grk, gb + G3, g_mh, G3, CD);
}

__global__ void gemm_iface(const float* __restrict__ hc, const float* __restrict__ Wif) {
    gemm_body(hc, Wif, nullptr, g_iface, IFC, CD);
}

// ---------------------------------------------------------------------------
// GRU combine: c = z*h + (1-z)*gelu(xh + r*rh)
// ---------------------------------------------------------------------------
__global__ void gru_combine(const float* __restrict__ h, float* __restrict__ hc_out) {
    int idx = blockIdx.x * blockDim.x + threadIdx.x;
    if (idx >= 128 * CD) return;
    int row = idx / CD, j = idx % CD;
    const float* mx = g_mx + row * G3;
    const float* mh = g_mh + row * G3;
    float z = sigmoidf_(mx[j] + mh[j]);
    float r = sigmoidf_(mx[CD + j] + mh[CD + j]);
    float hin = mx[2 * CD + j] + r * mh[2 * CD + j];
    float hh = hin * normcdff(hin);   // exact gelu
    float hv = h[idx];
    hc_out[idx] = z * hv + (1.f - z) * hh;
}

// ---------------------------------------------------------------------------
// Fused per-batch memory update (sort-free):
//   usage_n -> W_alloc via product-over-smaller-keys -> write content lookup
//   -> Ww -> Wp_n -> M_n
// 64 blocks x 512 threads
// ---------------------------------------------------------------------------
__global__ void memupdate_kernel(const float* __restrict__ W_read,
                                 const float* __restrict__ W_write,
                                 const float* __restrict__ usage,
                                 const float* __restrict__ M,
                                 const float* __restrict__ Wp,
                                 float* __restrict__ usage_out,
                                 float* __restrict__ Ww_out,
                                 float* __restrict__ Wp_out,
                                 float* __restrict__ Mn_out) {
    __shared__ float us[NMEM];
    __shared__ float wws[NMEM];
    __shared__ __align__(16) float nk[WD];
    __shared__ __align__(16) float es[WD];
    __shared__ __align__(16) float vs[WD];
    __shared__ float keyn[WD];
    __shared__ float sc[4];
    __shared__ float sb[16];
    int b = blockIdx.x, t = threadIdx.x;
    const float* ifw = g_iface + (2 * b + 1) * IFC;

    // --- usage_n ---
    float4 wr4 = *(const float4*)(W_read + (b * NMEM + t) * RH);
    float ret = (1.f - sigmoidf_(ifw[453]) * wr4.x)
              * (1.f - sigmoidf_(ifw[454]) * wr4.y)
              * (1.f - sigmoidf_(ifw[455]) * wr4.z)
              * (1.f - sigmoidf_(ifw[456]) * wr4.w);
    float u = usage[b * NMEM + t], w = W_write[b * NMEM + t];
    float un = (u + w - u * w) * ret;
    usage_out[b * NMEM + t] = un;
    us[t] = un;
    if (t < WD) {
        es[t] = sigmoidf_(ifw[325 + t]);
        vs[t] = ifw[389 + t];
        float kv = ifw[260 + t];
        keyn[t] = kv * kv;
    }
    __syncthreads();
    if (t == 0) {
        float s = 0.f;
        for (int i = 0; i < WD; i++) s += keyn[i];
        sc[0] = 1.f / sqrtf(fmaxf(s, 1e-12f));
        sc[1] = 1.f + softplusf_(ifw[324]);   // b_write
        sc[2] = sigmoidf_(ifw[457]);          // alloc_g
        sc[3] = sigmoidf_(ifw[458]);          // write_g
    }

    // --- W_alloc[n] = (1-u[n]) * prod_{key(m)<key(n)} u[m]  (sort-free) ---
    float p = 1.f;
#pragma unroll 8
    for (int m = 0; m < NMEM; m++) {
        float um = us[m];
        bool less = (um < un) || (um == un && m < t);
        p *= less ? um : 1.f;
    }
    float walloc = (1.f - un) * p;
    __syncthreads();
    if (t < WD) nk[t] = ifw[260 + t] * sc[0];
    __syncthreads();

    // --- write content lookup (float4) ---
    const float4* m4p = (const float4*)(M + (b * NMEM + t) * WD);
    const float4* nk4 = (const float4*)nk;
    float dot = 0.f, nrm = 0.f;
#pragma unroll
    for (int i = 0; i < 16; i++) {
        float4 m4 = m4p[i];
        float4 k4 = nk4[i];
        dot += m4.x * k4.x + m4.y * k4.y + m4.z * k4.z + m4.w * k4.w;
        nrm += m4.x * m4.x + m4.y * m4.y + m4.z * m4.z + m4.w * m4.w;
    }
    float s = dot * (1.f / sqrtf(fmaxf(nrm, 1e-12f))) * sc[1];
    float mxv = blk_red_max(s, sb, t);
    float e = expf(s - mxv);
    float ssum = blk_red_sum(e, sb, t);
    float wl = e / ssum;

    float ww = sc[3] * (sc[2] * walloc + (1.f - sc[2]) * wl);
    Ww_out[b * NMEM + t] = ww;
    wws[t] = ww;
    float wsum = blk_red_sum(ww, sb, t);   // barriers inside make wws visible
    // --- precedence ---
    Wp_out[b * NMEM + t] = (1.f - wsum) * Wp[b * NMEM + t] + ww;

    // --- M_n (float4, coalesced) ---
    const float4* M4 = (const float4*)(M + b * NMEM * WD);
    float4* Mn4 = (float4*)(Mn_out + b * NMEM * WD);
    const float4* es4 = (const float4*)es;
    const float4* vs4 = (const float4*)vs;
#pragma unroll
    for (int i = 0; i < 16; i++) {
        int idx4 = t + i * NMEM;       // 8192 float4 per batch
        int n = idx4 >> 4, w4 = idx4 & 15;
        float wwn = wws[n];
        float4 m4 = M4[idx4];
        float4 e4 = es4[w4];
        float4 v4 = vs4[w4];
        float4 o;
        o.x = m4.x * (1.f - wwn * e4.x) + wwn * v4.x;
        o.y = m4.y * (1.f - wwn * e4.y) + wwn * v4.y;
        o.z = m4.z * (1.f - wwn * e4.z) + wwn * v4.z;
        o.w = m4.w * (1.f - wwn * e4.w) + wwn * v4.w;
        Mn4[idx4] = o;
    }
}

// ---------------------------------------------------------------------------
// Link update + fused fwd/bwd partial reductions, 64x64 tiles, float4 I/O.
// grid (64 tiles, 64 batches), block 256
// ---------------------------------------------------------------------------
__global__ void link_kernel(const float* __restrict__ L, const float* __restrict__ Ww,
                            const float* __restrict__ Wp, const float* __restrict__ Wr,
                            float* __restrict__ Ln_out) {
    __shared__ __align__(16) float Ln_s[64][68];
    __shared__ float Wwi[64], Wwj[64], Wpj[64];
    __shared__ float Wri[64][4], Wrj[64][4];
    int b = blockIdx.y;
    int it = blockIdx.x >> 3, jt = blockIdx.x & 7;
    int i0 = it * 64, j0 = jt * 64;
    int t = threadIdx.x;
    if (t < 64) {
        Wwi[t] = Ww[b * NMEM + i0 + t];
        Wwj[t] = Ww[b * NMEM + j0 + t];
        Wpj[t] = Wp[b * NMEM + j0 + t];
    }
    {
        int n = t >> 2, r = t & 3;
        Wri[n][r] = Wr[(b * NMEM + i0 + n) * RH + r];
        Wrj[n][r] = Wr[(b * NMEM + j0 + n) * RH + r];
    }
    __syncthreads();
#pragma unroll
    for (int k = 0; k < 4; k++) {
        int e4 = t + k * 256;               // 1024 float4 in tile
        int il = e4 >> 4, j4 = (e4 & 15) * 4;
        long gidx = ((long)(b * NMEM + i0 + il)) * NMEM + j0 + j4;
        float4 l4 = *(const float4*)(L + gidx);
        float wwi = Wwi[il];
        float4 ln;
        ln.x = (1.f - wwi - Wwj[j4 + 0]) * l4.x + wwi * Wpj[j4 + 0];
        ln.y = (1.f - wwi - Wwj[j4 + 1]) * l4.y + wwi * Wpj[j4 + 1];
        ln.z = (1.f - wwi - Wwj[j4 + 2]) * l4.z + wwi * Wpj[j4 + 2];
        ln.w = (1.f - wwi - Wwj[j4 + 3]) * l4.w + wwi * Wpj[j4 + 3];
        if (it == jt) {
            if (il == j4 + 0) ln.x = 0.f;
            if (il == j4 + 1) ln.y = 0.f;
            if (il == j4 + 2) ln.z = 0.f;
            if (il == j4 + 3) ln.w = 0.f;
        }
        *(float4*)&Ln_s[il][j4] = ln;
        *(float4*)(Ln_out + gidx) = ln;
    }
    __syncthreads();
    {
        int il = t >> 2, r = t & 3;
        float accF = 0.f, accB = 0.f;
#pragma unroll
        for (int c = 0; c < 64; c++) {
            accF += Ln_s[il][c] * Wrj[c][r];   // fwd: row-reduction over j
            accB += Ln_s[c][il] * Wri[c][r];   // bwd: col-reduction over i
        }
        g_fwdpart[((b * 8 + jt) * NMEM + i0 + il) * RH + r] = accF;
        g_bwdpart[((b * 8 + it) * NMEM + j0 + il) * RH + r] = accB;
    }
}

// ---------------------------------------------------------------------------
// Fused: partial reduce + read content lookup + mode mix -> Wr_n
//        + read vectors + output projection. 64 blocks x 512 threads.
// ---------------------------------------------------------------------------
__global__ void read_fused_kernel(const float* __restrict__ Mn,
                                  const float* __restrict__ Wro,
                                  float* __restrict__ Wr_out,
                                  float* __restrict__ y_out) {
    __shared__ __align__(16) float fwd_s[NMEM * RH];   // 8KB
    __shared__ __align__(16) float bwd_s[NMEM * RH];   // 8KB
    __shared__ float Wrs[NMEM][RH];                    // 8KB
    __shared__ __align__(16) float nk[RH][WD];
    __shared__ float br[RH];
    __shared__ float m0s[RH], m1s[RH], m2s[RH];
    __shared__ float sb[16];
    __shared__ float part[512];
    __shared__ float rv[256];
    int b = blockIdx.x, t = threadIdx.x;
    const float* ifr = g_iface + (2 * b) * IFC;

    // reduce 8 partial tiles (float4: each thread owns 4 consecutive (n,r))
    {
        float4 f4 = make_float4(0.f, 0.f, 0.f, 0.f);
        float4 b4 = make_float4(0.f, 0.f, 0.f, 0.f);
#pragma unroll
        for (int c = 0; c < 8; c++) {
            const float4* fp = (const float4*)(g_fwdpart + (b * 8 + c) * (NMEM * RH)) + t;
            const float4* bp = (const float4*)(g_bwdpart + (b * 8 + c) * (NMEM * RH)) + t;
            float4 fv = *fp, bv = *bp;
            f4.x += fv.x; f4.y += fv.y; f4.z += fv.z; f4.w += fv.w;
            b4.x += bv.x; b4.y += bv.y; b4.z += bv.z; b4.w += bv.w;
        }
        ((float4*)fwd_s)[t] = f4;
        ((float4*)bwd_s)[t] = b4;
    }
    if (t < RH * WD) {
        int r = t >> 6, w = t & 63;
        nk[r][w] = ifr[r * WD + w];
    }
    if (t >= 256 && t < 256 + RH) {
        int r = t - 256;
        br[r] = 1.f + softplusf_(ifr[256 + r]);
        float a = ifr[459 + r], bb = ifr[463 + r], c = ifr[467 + r];
        float mx = fmaxf(a, fmaxf(bb, c));
        float ea = expf(a - mx), eb = expf(bb - mx), ec = expf(c - mx);
        float s = ea + eb + ec;
        m0s[r] = ea / s; m1s[r] = eb / s; m2s[r] = ec / s;
    }
    __syncthreads();
    if (t < RH) {
        float s = 0.f;
        for (int w = 0; w < WD; w++) { float v = nk[t][w]; s += v * v; }
        float rn = 1.f / sqrtf(fmaxf(s, 1e-12f));
        for (int w = 0; w < WD; w++) nk[t][w] *= rn;
    }
    __syncthreads();

    // content lookup (4 heads, float4)
    const float4* m4p = (const float4*)(Mn + (b * NMEM + t) * WD);
    float d[RH] = {0.f, 0.f, 0.f, 0.f};
    float nrm = 0.f;
#pragma unroll
    for (int i = 0; i < 16; i++) {
        float4 m4 = m4p[i];
        nrm += m4.x * m4.x + m4.y * m4.y + m4.z * m4.z + m4.w * m4.w;
#pragma unroll
        for (int r = 0; r < RH; r++) {
            float4 k4 = ((const float4*)nk[r])[i];
            d[r] += m4.x * k4.x + m4.y * k4.y + m4.z * k4.z + m4.w * k4.w;
        }
    }
    float rn = 1.f / sqrtf(fmaxf(nrm, 1e-12f));
    float wl[RH];
#pragma unroll
    for (int r = 0; r < RH; r++) {
        float s = d[r] * rn * br[r];
        float mxv = blk_red_max(s, sb, t);
        float e = expf(s - mxv);
        float ssum = blk_red_sum(e, sb, t);
        wl[r] = e / ssum;
    }
#pragma unroll
    for (int r = 0; r < RH; r++) {
        float v = m0s[r] * bwd_s[t * RH + r] + m1s[r] * wl[r] + m2s[r] * fwd_s[t * RH + r];
        Wr_out[(b * NMEM + t) * RH + r] = v;
        Wrs[t][r] = v;
    }
    __syncthreads();

    // read vectors: rv[r*64+w] = sum_n Mn[n,w] * Wr[n,r]; all 512 threads
    {
        int half = t >> 8, tt = t & 255;
        int r = tt >> 6, w = tt & 63;
        int n0 = half * 256;
        float acc = 0.f;
#pragma unroll 8
        for (int n = 0; n < 256; n++)
            acc += Mn[(b * NMEM + n0 + n) * WD + w] * Wrs[n0 + n][r];
        part[t] = acc;
    }
    __syncthreads();
    if (t < 256) rv[t] = part[t] + part[256 + t];
    __syncthreads();
    // y = rv @ W_read_out ; all 512 threads (k-split)
    {
        int half = t >> 8, tt = t & 255;
        int k0 = half * 128;
        float ya = 0.f;
#pragma unroll 8
        for (int k = 0; k < 128; k++) ya += rv[k0 + k] * Wro[(k0 + k) * OUTD + tt];
        part[t] = ya;
    }
    __syncthreads();
    if (t < 256) y_out[b * OUTD + t] = part[t] + part[256 + t];
}

// ---------------------------------------------------------------------------
extern "C" void kernel_launch(void* const* d_in, const int* in_sizes, int n_in,
                              void* d_out, int out_size) {
    const float* inputs   = (const float*)d_in[0];
    const float* M        = (const float*)d_in[1];
    const float* usage    = (const float*)d_in[2];
    const float* L        = (const float*)d_in[3];
    const float* Wp       = (const float*)d_in[4];
    const float* W_read   = (const float*)d_in[5];
    const float* W_write  = (const float*)d_in[6];
    const float* h_ctrl   = (const float*)d_in[7];
    const float* W_iface  = (const float*)d_in[8];
    const float* W_rdout  = (const float*)d_in[9];
    const float* gru_k    = (const float*)d_in[10];
    const float* gru_rk   = (const float*)d_in[11];
    const float* gru_b    = (const float*)d_in[12];

    float* out = (float*)d_out;
    float* o_y    = out + OFF_Y;
    float* o_mn   = out + OFF_MN;
    float* o_use  = out + OFF_USAGE;
    float* o_ln   = out + OFF_LN;
    float* o_wp   = out + OFF_WP;
    float* o_wr   = out + OFF_WR;
    float* o_ww   = out + OFF_WW;
    float* o_hc   = out + OFF_HC;

    // 1) GRU mats mx & mh in one launch (independent, z selects)
    gemm_gru<<<dim3((G3 + 31) / 32, 4, 2), 128>>>(inputs, h_ctrl, gru_k, gru_rk, gru_b);
    // 2) combine -> hc
    gru_combine<<<(128 * CD + 255) / 256, 256>>>(h_ctrl, o_hc);
    // 3) interface = hc @ W_interface
    gemm_iface<<<dim3((IFC + 31) / 32, 4), 128>>>(o_hc, W_iface);
    // 4) fused usage + alloc + write lookup + Ww + Wp + M_n (sort-free)
    memupdate_kernel<<<BSZ, NMEM>>>(W_read, W_write, usage, M, Wp,
                                    o_use, o_ww, o_wp, o_mn);
    // 5) link update fused with fwd/bwd partials
    link_kernel<<<dim3(64, BSZ), 256>>>(L, o_ww, Wp, W_read, o_ln);
    // 6) fused reduce + read lookup + Wr + read vectors + y
    read_fused_kernel<<<BSZ, NMEM>>>(o_mn, W_rdout, o_wr, o_y);
}